// round 11
// baseline (speedup 1.0000x reference)
#include <cuda_runtime.h>
#include <cuda_fp16.h>

// M is [512, 65536] fp32. Sinkhorn; trip count in {1, 51, 100}; this input exits at 1.
// Strategy: ONE streamed DRAM pass over M builds fp16 K=exp(-20M) (64MB, L2-resident);
// phase C and the err pass read K from L2. Loss recovers m = -ln(k)/20 via MUFU log.
#define NR    512
#define NC    65536
#define GRID  128              // <= SM count: wave-1 co-residency guaranteed
#define TPB   512
#define CPB   512              // columns per block (full column stripe)

// Persistent scratch (__device__ globals per allocation rule)
__device__ __half   g_K[(size_t)NR * NC];   // 64 MB fp16 kernel matrix (L2-resident)
__device__ float    g_sPart[GRID * NR];     // row partials of K.v
__device__ float    g_qPart[GRID * NR];     // row partials of (K*M).v  (loss)
__device__ float    g_u[NR];
__device__ float    g_errPart[GRID];
__device__ float    g_lossPart[GRID];
__device__ int      g_done;
__device__ unsigned g_bar = 0;
__device__ volatile unsigned g_gen = 0;     // monotone across graph replays

// Grid barrier: GRID <= #SMs -> cannot deadlock. Spin cap = escape hatch only.
__device__ __forceinline__ void gsync(unsigned &phase) {
    __syncthreads();
    if (threadIdx.x == 0) {
        ++phase;
        __threadfence();
        if (atomicAdd(&g_bar, 1u) == GRID - 1u) {
            g_bar = 0u;
            __threadfence();
            g_gen = phase;
        } else {
            unsigned spins = 0;
            while (g_gen < phase) {
                __nanosleep(64);
                if (++spins > (1u << 18)) break;
            }
        }
    }
    __syncthreads();
}

__device__ __forceinline__ float blockReduce512(float x, float* sh) {
    const int t = threadIdx.x;
    sh[t] = x; __syncthreads();
    if (t < 256) sh[t] += sh[t + 256];
    __syncthreads();
    if (t < 128) sh[t] += sh[t + 128];
    __syncthreads();
    if (t < 64)  sh[t] += sh[t + 64];
    __syncthreads();
    if (t < 32) {
        float v = sh[t] + sh[t + 32];
        #pragma unroll
        for (int o = 16; o; o >>= 1) v += __shfl_down_sync(0xffffffffu, v, o);
        if (t == 0) sh[0] = v;
    }
    __syncthreads();
    float r = sh[0];
    __syncthreads();
    return r;
}

__global__ void __launch_bounds__(TPB, 1)
sinkhorn_all(const float* __restrict__ M, float* __restrict__ out) {
    __shared__ float sh[TPB];
    __shared__ float sh2[TPB];
    __shared__ float sh_u[NR];
    __shared__ float sh_v[CPB];    // this block's v stripe (current iteration)
    __shared__ float sh_l4[4];
    const int tid = threadIdx.x;
    const int bid = blockIdx.x;
    unsigned phase = g_gen;        // continue barrier generation across graph replays

    const int j    = bid * CPB + tid;   // owned column (pass 1)
    const int w    = tid >> 5, lane = tid & 31;     // phase C row mapping
    const int rr4  = tid >> 7, p128 = tid & 127;    // u-reduce mapping (4 rows/block)
    const int jj   = tid & 255, h = tid >> 8;       // column-pair mapping (err / phase A)

    // ===== pass 1: stream M (evict-first), store fp16 K, col-sum -> v1 =====
    {
        const float* mp = M + j;
        __half*      kp = g_K + j;
        float t0 = 0.0f, t1 = 0.0f;
        #pragma unroll 8
        for (int r = 0; r < NR; r += 2) {
            float m0 = __ldcs(&mp[(size_t)r * NC]);
            float m1 = __ldcs(&mp[(size_t)(r + 1) * NC]);
            float k0 = __expf(-20.0f * m0);
            float k1 = __expf(-20.0f * m1);
            kp[(size_t)r * NC]       = __float2half(k0);
            kp[(size_t)(r + 1) * NC] = __float2half(k1);
            t0 += k0; t1 += k1;
        }
        float t = (t0 + t1) * (1.0f / NR);
        sh_v[tid] = (1.0f / NC) / (t + 1e-16f);
    }
    __syncthreads();               // K stripe + sh_v visible within block

    // ---- phase C: row partials of K.v and (K*m).v over own stripe (L2 hits),
    // then partitioned u-reduce: block b owns rows [4b,4b+4) -> g_u, g_lossPart.
    #define PHASE_C()                                                              \
    {                                                                              \
        _Pragma("unroll 2")                                                        \
        for (int rr = 0; rr < 32; ++rr) {                                          \
            const int row = w * 32 + rr;                                           \
            const uint4* kp4 = (const uint4*)(g_K + (size_t)row * NC + bid * CPB); \
            const float4* v4 = (const float4*)sh_v;                                \
            float s = 0.0f, qa = 0.0f;                                             \
            _Pragma("unroll")                                                      \
            for (int c = lane; c < 64; c += 32) {                                  \
                uint4 kk = kp4[c];                                                 \
                const __half2* kh = (const __half2*)&kk;                           \
                float4 va = v4[2 * c], vb = v4[2 * c + 1];                         \
                _Pragma("unroll")                                                  \
                for (int q2 = 0; q2 < 4; ++q2) {                                   \
                    float2 kf = __half22float2(kh[q2]);                            \
                    const float* vp = (q2 < 2) ? (const float*)&va : (const float*)&vb; \
                    float vx = vp[(q2 & 1) * 2], vy = vp[(q2 & 1) * 2 + 1];        \
                    float p0 = -0.05f * kf.x * __logf(kf.x);                       \
                    float p1 = -0.05f * kf.y * __logf(kf.y);                       \
                    p0 = (kf.x > 0.0f) ? p0 : 0.0f;                                \
                    p1 = (kf.y > 0.0f) ? p1 : 0.0f;                                \
                    s  = fmaf(kf.x, vx, s);  s  = fmaf(kf.y, vy, s);               \
                    qa = fmaf(p0,  vx, qa);  qa = fmaf(p1,  vy, qa);               \
                }                                                                  \
            }                                                                      \
            _Pragma("unroll")                                                      \
            for (int o = 16; o; o >>= 1) {                                         \
                s  += __shfl_down_sync(0xffffffffu, s,  o);                        \
                qa += __shfl_down_sync(0xffffffffu, qa, o);                        \
            }                                                                      \
            if (lane == 0) {                                                       \
                g_sPart[bid * NR + row] = s;                                       \
                g_qPart[bid * NR + row] = qa;                                      \
            }                                                                      \
        }                                                                          \
        gsync(phase);                                                              \
        {                                                                          \
            const int row2 = bid * 4 + rr4;                                        \
            float su = __ldcg(&g_sPart[p128 * NR + row2]);                         \
            float qu = __ldcg(&g_qPart[p128 * NR + row2]);                         \
            sh[tid] = su; sh2[tid] = qu; __syncthreads();                          \
            if (p128 < 64) { sh[tid] += sh[tid + 64]; sh2[tid] += sh2[tid + 64]; } \
            __syncthreads();                                                       \
            if (p128 < 32) {                                                       \
                float x = sh[tid] + sh[tid + 32];                                  \
                float y = sh2[tid] + sh2[tid + 32];                                \
                _Pragma("unroll")                                                  \
                for (int o = 16; o; o >>= 1) {                                     \
                    x += __shfl_down_sync(0xffffffffu, x, o);                      \
                    y += __shfl_down_sync(0xffffffffu, y, o);                      \
                }                                                                  \
                if (p128 == 0) {                                                   \
                    float ur = (1.0f / NR) / (x + 1e-16f);                         \
                    g_u[row2] = ur;                                                \
                    sh_l4[rr4] = ur * y;                                           \
                }                                                                  \
            }                                                                      \
            __syncthreads();                                                       \
            if (tid == 0)                                                          \
                g_lossPart[bid] = (sh_l4[0] + sh_l4[1]) + (sh_l4[2] + sh_l4[3]);   \
            gsync(phase);                                                          \
        }                                                                          \
    }

    // ---- column pass over fp16 K: tp = K^T u. DO_ERR: err check + verdict;
    // always produces the next v into sh_v. 256 col-pairs x 2 row-halves.
    #define COL_PASS(DO_ERR, done_var)                                             \
    {                                                                              \
        sh_u[tid] = __ldcg(&g_u[tid]); __syncthreads();                            \
        const __half2* kc = (const __half2*)g_K                                    \
                            + (size_t)(h * 256) * (NC / 2) + (size_t)(bid * 256 + jj); \
        float s0 = 0.0f, s1 = 0.0f;                                                \
        _Pragma("unroll 16")                                                       \
        for (int r = 0; r < 256; ++r) {                                            \
            float2 kf = __half22float2(kc[(size_t)r * (NC / 2)]);                  \
            float  u  = sh_u[h * 256 + r];                                         \
            s0 = fmaf(kf.x, u, s0);                                                \
            s1 = fmaf(kf.y, u, s1);                                                \
        }                                                                          \
        sh[tid] = s0; sh2[tid] = s1; __syncthreads();                              \
        float e = 0.0f, vn0 = 0.0f, vn1 = 0.0f;                                    \
        if (tid < 256) {                                                           \
            float tp0 = sh[tid] + sh[tid + 256];                                   \
            float tp1 = sh2[tid] + sh2[tid + 256];                                 \
            vn0 = (1.0f / NC) / (tp0 + 1e-16f);                                    \
            vn1 = (1.0f / NC) / (tp1 + 1e-16f);                                    \
            if (DO_ERR)                                                            \
                e = fabsf(sh_v[2 * tid] * tp0 - (1.0f / NC))                       \
                  + fabsf(sh_v[2 * tid + 1] * tp1 - (1.0f / NC));                  \
        }                                                                          \
        __syncthreads();                                                           \
        if (DO_ERR) {                                                              \
            float eb = blockReduce512(e, sh);                                      \
            if (tid == 0) g_errPart[bid] = eb;                                     \
            gsync(phase);                                                          \
            if (bid == 0) {                                                        \
                float ep = (tid < GRID) ? __ldcg(&g_errPart[tid]) : 0.0f;          \
                float et = blockReduce512(ep, sh);                                 \
                int dn = (et <= 0.005f);                                           \
                if (dn) {                                                          \
                    float lp = (tid < GRID) ? __ldcg(&g_lossPart[tid]) : 0.0f;     \
                    float lt = blockReduce512(lp, sh);                             \
                    if (tid == 0) out[0] = 100.0f * lt;                            \
                }                                                                  \
                if (tid == 0) g_done = dn;                                         \
            }                                                                      \
            gsync(phase);                                                          \
            done_var = __ldcg(&g_done);                                            \
        }                                                                          \
        if (tid < 256) { sh_v[2 * tid] = vn0; sh_v[2 * tid + 1] = vn1; }           \
        __syncthreads();                                                           \
    }

    // ===== c = 1: phase C -> u_1 (+loss); err check (4 gsyncs on fast path) =====
    PHASE_C();
    int done = 0;
    COL_PASS(1, done);
    if (done) return;                         // trip-1 fast path ends here

    // ===== c = 2..100 (dead for this input; kept correct) =====
    for (int c = 2; c <= 100; ++c) {
        if (c != 2 && c != 52) {
            int dummy = 0;
            COL_PASS(0, dummy);               // phase A: v_c from fp16 K
        } // c==2 / c==52: v already produced by COL_PASS(1, ...)

        PHASE_C();                            // u_c (+ loss partials)

        if (c == 51) {
            COL_PASS(1, done);
            if (done) return;
        }
    }

    // ===== cap exit (cpt=100): loss partials from last PHASE_C =====
    if (bid == 0) {
        float lp = (tid < GRID) ? __ldcg(&g_lossPart[tid]) : 0.0f;
        float lt = blockReduce512(lp, sh);
        if (tid == 0) out[0] = 100.0f * lt;
    }
}

extern "C" void kernel_launch(void* const* d_in, const int* in_sizes, int n_in,
                              void* d_out, int out_size) {
    const float* M = (const float*)d_in[0];
    float* out = (float*)d_out;
    sinkhorn_all<<<GRID, TPB>>>(M, out);
}

// round 12
// speedup vs baseline: 1.2012x; 1.2012x over previous
#include <cuda_runtime.h>
#include <cuda_fp16.h>

// M is [512, 65536] fp32. Sinkhorn; trip count in {1, 51, 100}; this input exits at 1.
// ONE streamed DRAM pass over M builds fp16 K=exp(-20M) (64MB, L2-resident); phase C
// and the err pass read K from L2. Loss recovers m = -ln(k)/20 via MUFU log.
// R12: fixed register->lmem demotion in phase C (conditional pointer-to-register).
#define NR    512
#define NC    65536
#define GRID  128              // <= SM count: wave-1 co-residency guaranteed
#define TPB   512
#define CPB   512              // columns per block (full column stripe)

// Persistent scratch (__device__ globals per allocation rule)
__device__ __half   g_K[(size_t)NR * NC];   // 64 MB fp16 kernel matrix (L2-resident)
__device__ float    g_sPart[GRID * NR];     // row partials of K.v
__device__ float    g_qPart[GRID * NR];     // row partials of (K*M).v (pre-scaled -0.05)
__device__ float    g_u[NR];
__device__ float    g_errPart[GRID];
__device__ float    g_lossPart[GRID];
__device__ int      g_done;
__device__ unsigned g_bar = 0;
__device__ volatile unsigned g_gen = 0;     // monotone across graph replays

// Grid barrier: GRID <= #SMs -> cannot deadlock. Spin cap = escape hatch only.
__device__ __forceinline__ void gsync(unsigned &phase) {
    __syncthreads();
    if (threadIdx.x == 0) {
        ++phase;
        __threadfence();
        if (atomicAdd(&g_bar, 1u) == GRID - 1u) {
            g_bar = 0u;
            __threadfence();
            g_gen = phase;
        } else {
            unsigned spins = 0;
            while (g_gen < phase) {
                __nanosleep(64);
                if (++spins > (1u << 18)) break;
            }
        }
    }
    __syncthreads();
}

__device__ __forceinline__ float blockReduce512(float x, float* sh) {
    const int t = threadIdx.x;
    sh[t] = x; __syncthreads();
    if (t < 256) sh[t] += sh[t + 256];
    __syncthreads();
    if (t < 128) sh[t] += sh[t + 128];
    __syncthreads();
    if (t < 64)  sh[t] += sh[t + 64];
    __syncthreads();
    if (t < 32) {
        float v = sh[t] + sh[t + 32];
        #pragma unroll
        for (int o = 16; o; o >>= 1) v += __shfl_down_sync(0xffffffffu, v, o);
        if (t == 0) sh[0] = v;
    }
    __syncthreads();
    float r = sh[0];
    __syncthreads();
    return r;
}

__global__ void __launch_bounds__(TPB, 1)
sinkhorn_all(const float* __restrict__ M, float* __restrict__ out) {
    __shared__ float sh[TPB];
    __shared__ float sh2[TPB];
    __shared__ float sh_u[NR];
    __shared__ float sh_v[CPB];    // this block's v stripe (current iteration)
    __shared__ float sh_l4[4];
    const int tid = threadIdx.x;
    const int bid = blockIdx.x;
    unsigned phase = g_gen;        // continue barrier generation across graph replays

    const int w    = tid >> 5, lane = tid & 31;     // phase C row mapping
    const int rr4  = tid >> 7, p128 = tid & 127;    // u-reduce mapping (4 rows/block)
    const int jj   = tid & 255, h = tid >> 8;       // column-pair mapping

    // ===== pass 1: stream M (evict-first), store fp16 K, col-sums -> v1 =====
    // Thread owns column pair (2*jj, 2*jj+1) over its row half: float2 / half2.
    {
        const float2* mp = (const float2*)(M + (size_t)h * 256 * NC) + (size_t)(bid * 256 + jj);
        __half2*      kp = (__half2*)(g_K + (size_t)h * 256 * NC) + (size_t)(bid * 256 + jj);
        float t0 = 0.0f, t1 = 0.0f;
        #pragma unroll 8
        for (int r = 0; r < 256; ++r) {
            float2 m = __ldcs(&mp[(size_t)r * (NC / 2)]);
            float k0 = __expf(-20.0f * m.x);
            float k1 = __expf(-20.0f * m.y);
            kp[(size_t)r * (NC / 2)] = __floats2half2_rn(k0, k1);
            t0 += k0; t1 += k1;
        }
        sh[tid] = t0; sh2[tid] = t1; __syncthreads();
        if (tid < 256) {
            float T0 = (sh[tid] + sh[tid + 256]) * (1.0f / NR);
            float T1 = (sh2[tid] + sh2[tid + 256]) * (1.0f / NR);
            sh_v[2 * tid]     = (1.0f / NC) / (T0 + 1e-16f);
            sh_v[2 * tid + 1] = (1.0f / NC) / (T1 + 1e-16f);
        }
        __syncthreads();
    }

    // ---- phase C: row partials of K.v and (K*m).v over own stripe (L2 hits).
    // Explicit component access only (no pointers to registers -> no lmem).
    // qa accumulates k*ln(k)*v; scaled by -0.05 once at store.
    #define PHASE_C()                                                              \
    {                                                                              \
        _Pragma("unroll 2")                                                        \
        for (int rr = 0; rr < 32; ++rr) {                                          \
            const int row = w * 32 + rr;                                           \
            const uint4* kp4 = (const uint4*)(g_K + (size_t)row * NC + bid * CPB); \
            const float4* v4 = (const float4*)sh_v;                                \
            float s = 0.0f, qa = 0.0f;                                             \
            _Pragma("unroll")                                                      \
            for (int c = lane; c < 64; c += 32) {                                  \
                uint4 kk = kp4[c];                                                 \
                const __half2* kh = (const __half2*)&kk;                           \
                float4 va = v4[2 * c], vb = v4[2 * c + 1];                         \
                float2 f0 = __half22float2(kh[0]);                                 \
                float2 f1 = __half22float2(kh[1]);                                 \
                float2 f2 = __half22float2(kh[2]);                                 \
                float2 f3 = __half22float2(kh[3]);                                 \
                s  = fmaf(f0.x, va.x, s);                                          \
                qa = fmaf(f0.x * __logf(fmaxf(f0.x, 1e-38f)), va.x, qa);           \
                s  = fmaf(f0.y, va.y, s);                                          \
                qa = fmaf(f0.y * __logf(fmaxf(f0.y, 1e-38f)), va.y, qa);           \
                s  = fmaf(f1.x, va.z, s);                                          \
                qa = fmaf(f1.x * __logf(fmaxf(f1.x, 1e-38f)), va.z, qa);           \
                s  = fmaf(f1.y, va.w, s);                                          \
                qa = fmaf(f1.y * __logf(fmaxf(f1.y, 1e-38f)), va.w, qa);           \
                s  = fmaf(f2.x, vb.x, s);                                          \
                qa = fmaf(f2.x * __logf(fmaxf(f2.x, 1e-38f)), vb.x, qa);           \
                s  = fmaf(f2.y, vb.y, s);                                          \
                qa = fmaf(f2.y * __logf(fmaxf(f2.y, 1e-38f)), vb.y, qa);           \
                s  = fmaf(f3.x, vb.z, s);                                          \
                qa = fmaf(f3.x * __logf(fmaxf(f3.x, 1e-38f)), vb.z, qa);           \
                s  = fmaf(f3.y, vb.w, s);                                          \
                qa = fmaf(f3.y * __logf(fmaxf(f3.y, 1e-38f)), vb.w, qa);           \
            }                                                                      \
            _Pragma("unroll")                                                      \
            for (int o = 16; o; o >>= 1) {                                         \
                s  += __shfl_down_sync(0xffffffffu, s,  o);                        \
                qa += __shfl_down_sync(0xffffffffu, qa, o);                        \
            }                                                                      \
            if (lane == 0) {                                                       \
                g_sPart[bid * NR + row] = s;                                       \
                g_qPart[bid * NR + row] = -0.05f * qa;                             \
            }                                                                      \
        }                                                                          \
        gsync(phase);                                                              \
        {                                                                          \
            const int row2 = bid * 4 + rr4;                                        \
            float su = __ldcg(&g_sPart[p128 * NR + row2]);                         \
            float qu = __ldcg(&g_qPart[p128 * NR + row2]);                         \
            sh[tid] = su; sh2[tid] = qu; __syncthreads();                          \
            if (p128 < 64) { sh[tid] += sh[tid + 64]; sh2[tid] += sh2[tid + 64]; } \
            __syncthreads();                                                       \
            if (p128 < 32) {                                                       \
                float x = sh[tid] + sh[tid + 32];                                  \
                float y = sh2[tid] + sh2[tid + 32];                                \
                _Pragma("unroll")                                                  \
                for (int o = 16; o; o >>= 1) {                                     \
                    x += __shfl_down_sync(0xffffffffu, x, o);                      \
                    y += __shfl_down_sync(0xffffffffu, y, o);                      \
                }                                                                  \
                if (p128 == 0) {                                                   \
                    float ur = (1.0f / NR) / (x + 1e-16f);                         \
                    g_u[row2] = ur;                                                \
                    sh_l4[rr4] = ur * y;                                           \
                }                                                                  \
            }                                                                      \
            __syncthreads();                                                       \
            if (tid == 0)                                                          \
                g_lossPart[bid] = (sh_l4[0] + sh_l4[1]) + (sh_l4[2] + sh_l4[3]);   \
            gsync(phase);                                                          \
        }                                                                          \
    }

    // ---- column pass over fp16 K: tp = K^T u. DO_ERR: err check + verdict;
    // always produces the next v into sh_v. 256 col-pairs x 2 row-halves.
    #define COL_PASS(DO_ERR, done_var)                                             \
    {                                                                              \
        sh_u[tid] = __ldcg(&g_u[tid]); __syncthreads();                            \
        const __half2* kc = (const __half2*)g_K                                    \
                            + (size_t)(h * 256) * (NC / 2) + (size_t)(bid * 256 + jj); \
        float s0 = 0.0f, s1 = 0.0f;                                                \
        _Pragma("unroll 16")                                                       \
        for (int r = 0; r < 256; ++r) {                                            \
            float2 kf = __half22float2(kc[(size_t)r * (NC / 2)]);                  \
            float  u  = sh_u[h * 256 + r];                                         \
            s0 = fmaf(kf.x, u, s0);                                                \
            s1 = fmaf(kf.y, u, s1);                                                \
        }                                                                          \
        sh[tid] = s0; sh2[tid] = s1; __syncthreads();                              \
        float e = 0.0f, vn0 = 0.0f, vn1 = 0.0f;                                    \
        if (tid < 256) {                                                           \
            float tp0 = sh[tid] + sh[tid + 256];                                   \
            float tp1 = sh2[tid] + sh2[tid + 256];                                 \
            vn0 = (1.0f / NC) / (tp0 + 1e-16f);                                    \
            vn1 = (1.0f / NC) / (tp1 + 1e-16f);                                    \
            if (DO_ERR)                                                            \
                e = fabsf(sh_v[2 * tid] * tp0 - (1.0f / NC))                       \
                  + fabsf(sh_v[2 * tid + 1] * tp1 - (1.0f / NC));                  \
        }                                                                          \
        __syncthreads();                                                           \
        if (DO_ERR) {                                                              \
            float eb = blockReduce512(e, sh);                                      \
            if (tid == 0) g_errPart[bid] = eb;                                     \
            gsync(phase);                                                          \
            if (bid == 0) {                                                        \
                float ep = (tid < GRID) ? __ldcg(&g_errPart[tid]) : 0.0f;          \
                float et = blockReduce512(ep, sh);                                 \
                int dn = (et <= 0.005f);                                           \
                if (dn) {                                                          \
                    float lp = (tid < GRID) ? __ldcg(&g_lossPart[tid]) : 0.0f;     \
                    float lt = blockReduce512(lp, sh);                             \
                    if (tid == 0) out[0] = 100.0f * lt;                            \
                }                                                                  \
                if (tid == 0) g_done = dn;                                         \
            }                                                                      \
            gsync(phase);                                                          \
            done_var = __ldcg(&g_done);                                            \
        }                                                                          \
        if (tid < 256) { sh_v[2 * tid] = vn0; sh_v[2 * tid + 1] = vn1; }           \
        __syncthreads();                                                           \
    }

    // ===== c = 1: phase C -> u_1 (+loss); err check (4 gsyncs on fast path) =====
    PHASE_C();
    int done = 0;
    COL_PASS(1, done);
    if (done) return;                         // trip-1 fast path ends here

    // ===== c = 2..100 (dead for this input; kept correct) =====
    for (int c = 2; c <= 100; ++c) {
        if (c != 2 && c != 52) {
            int dummy = 0;
            COL_PASS(0, dummy);               // phase A: v_c from fp16 K
        } // c==2 / c==52: v already produced by COL_PASS(1, ...)

        PHASE_C();                            // u_c (+ loss partials)

        if (c == 51) {
            COL_PASS(1, done);
            if (done) return;
        }
    }

    // ===== cap exit (cpt=100): loss partials from last PHASE_C =====
    if (bid == 0) {
        float lp = (tid < GRID) ? __ldcg(&g_lossPart[tid]) : 0.0f;
        float lt = blockReduce512(lp, sh);
        if (tid == 0) out[0] = 100.0f * lt;
    }
}

extern "C" void kernel_launch(void* const* d_in, const int* in_sizes, int n_in,
                              void* d_out, int out_size) {
    const float* M = (const float*)d_in[0];
    float* out = (float*)d_out;
    sinkhorn_all<<<GRID, TPB>>>(M, out);
}

// round 13
// speedup vs baseline: 1.5548x; 1.2944x over previous
#include <cuda_runtime.h>
#include <cuda_fp16.h>

// M is [512, 65536] fp32. Sinkhorn; trip count in {1, 51, 100}; this input exits at 1.
// R13: exp computed ONCE (33.5M MUFU). Pass 1 streams M (DRAM, evict-first), stores
// fp16 K=exp(-20M) AND fp16 KM=K*M (128MB, ~L2-resident). All later passes read
// K/KM from L2 with deep load batching; no exp/log anywhere past pass 1.
#define NR    512
#define NC    65536
#define GRID  128              // <= SM count: wave-1 co-residency guaranteed
#define TPB   512
#define CPB   512              // columns per block (full column stripe)

// Persistent scratch (__device__ globals per allocation rule)
__device__ __half   g_K [(size_t)NR * NC];  // 64 MB fp16 kernel matrix
__device__ __half   g_KM[(size_t)NR * NC];  // 64 MB fp16 K*M (loss integrand)
__device__ float    g_sPart[GRID * NR];     // row partials of K.v
__device__ float    g_qPart[GRID * NR];     // row partials of KM.v
__device__ float    g_u[NR];
__device__ float    g_errPart[GRID];
__device__ float    g_lossPart[GRID];
__device__ int      g_done;
__device__ unsigned g_bar = 0;
__device__ volatile unsigned g_gen = 0;     // monotone across graph replays

// Grid barrier: GRID <= #SMs -> cannot deadlock. Spin cap = escape hatch only.
__device__ __forceinline__ void gsync(unsigned &phase) {
    __syncthreads();
    if (threadIdx.x == 0) {
        ++phase;
        __threadfence();
        if (atomicAdd(&g_bar, 1u) == GRID - 1u) {
            g_bar = 0u;
            __threadfence();
            g_gen = phase;
        } else {
            unsigned spins = 0;
            while (g_gen < phase) {
                __nanosleep(64);
                if (++spins > (1u << 18)) break;
            }
        }
    }
    __syncthreads();
}

__device__ __forceinline__ float blockReduce512(float x, float* sh) {
    const int t = threadIdx.x;
    sh[t] = x; __syncthreads();
    if (t < 256) sh[t] += sh[t + 256];
    __syncthreads();
    if (t < 128) sh[t] += sh[t + 128];
    __syncthreads();
    if (t < 64)  sh[t] += sh[t + 64];
    __syncthreads();
    if (t < 32) {
        float v = sh[t] + sh[t + 32];
        #pragma unroll
        for (int o = 16; o; o >>= 1) v += __shfl_down_sync(0xffffffffu, v, o);
        if (t == 0) sh[0] = v;
    }
    __syncthreads();
    float r = sh[0];
    __syncthreads();
    return r;
}

// 2 halfs packed in a u32 -> float2 (constant-index bit access only; no lmem)
__device__ __forceinline__ float2 h2f(unsigned v) {
    union { unsigned u; __half2 h; } cv; cv.u = v;
    return __half22float2(cv.h);
}
// dot of 8 packed halfs (uint4) with 8 floats (2x float4)
__device__ __forceinline__ float dot8(uint4 kk, float4 va, float4 vb) {
    float2 f0 = h2f(kk.x), f1 = h2f(kk.y), f2 = h2f(kk.z), f3 = h2f(kk.w);
    float s = f3.y * vb.w;
    s = fmaf(f3.x, vb.z, s); s = fmaf(f2.y, vb.y, s); s = fmaf(f2.x, vb.x, s);
    s = fmaf(f1.y, va.w, s); s = fmaf(f1.x, va.z, s);
    s = fmaf(f0.y, va.y, s); s = fmaf(f0.x, va.x, s);
    return s;
}

__global__ void __launch_bounds__(TPB, 1)
sinkhorn_all(const float* __restrict__ M, float* __restrict__ out) {
    __shared__ float sh[TPB];
    __shared__ float sh2[TPB];
    __shared__ float sh_u[NR];
    __shared__ float sh_v[CPB];        // this block's v stripe
    __shared__ float shcol[16][CPB];   // cross-warp column-partial staging (32KB)
    __shared__ float sh_l4[4];
    const int tid = threadIdx.x;
    const int bid = blockIdx.x;
    unsigned phase = g_gen;            // continue barrier generation across replays

    const int w    = tid >> 5, lane = tid & 31;
    const int rr4  = tid >> 7, p128 = tid & 127;   // u-reduce mapping (4 rows/block)

    // ===== pass 1: stream M row-major (evict-first), store fp16 K and KM,
    // accumulate per-thread column sums -> v1. The ONLY exp in the kernel. =====
    {
        float t16[16];
        #pragma unroll
        for (int i = 0; i < 16; ++i) t16[i] = 0.0f;
        #pragma unroll 2
        for (int r = 0; r < 32; ++r) {
            const int row = w * 32 + r;
            const float4* m4 = (const float4*)(M + (size_t)row * NC + bid * CPB);
            uint2* kp = (uint2*)(g_K  + (size_t)row * NC + bid * CPB);
            uint2* qp = (uint2*)(g_KM + (size_t)row * NC + bid * CPB);
            #pragma unroll
            for (int g = 0; g < 4; ++g) {
                const int i = lane + 32 * g;
                float4 m = __ldcs(&m4[i]);
                float k0 = __expf(-20.0f * m.x);
                float k1 = __expf(-20.0f * m.y);
                float k2 = __expf(-20.0f * m.z);
                float k3 = __expf(-20.0f * m.w);
                t16[4 * g + 0] += k0; t16[4 * g + 1] += k1;
                t16[4 * g + 2] += k2; t16[4 * g + 3] += k3;
                union { __half2 h; unsigned u; } a, b, c, d;
                a.h = __floats2half2_rn(k0, k1);
                b.h = __floats2half2_rn(k2, k3);
                c.h = __floats2half2_rn(k0 * m.x, k1 * m.y);
                d.h = __floats2half2_rn(k2 * m.z, k3 * m.w);
                kp[i] = make_uint2(a.u, b.u);
                qp[i] = make_uint2(c.u, d.u);
            }
        }
        #pragma unroll
        for (int g = 0; g < 4; ++g)
            #pragma unroll
            for (int q = 0; q < 4; ++q)
                shcol[w][(lane + 32 * g) * 4 + q] = t16[4 * g + q];
        __syncthreads();
        float t = 0.0f;
        #pragma unroll
        for (int w2 = 0; w2 < 16; ++w2) t += shcol[w2][tid];
        sh_v[tid] = (1.0f / NC) / (t * (1.0f / NR) + 1e-16f);
        __syncthreads();
    }

    // ---- phase C: row partials of K.v and KM.v over own stripe (L2 hits).
    // 4-row batches, 8 independent uint4 loads before use; v hoisted to regs.
    #define PHASE_C()                                                              \
    {                                                                              \
        const float4* v4 = (const float4*)sh_v;                                    \
        const float4 va0 = v4[2 * lane],        vb0 = v4[2 * lane + 1];            \
        const float4 va1 = v4[2 * (lane + 32)], vb1 = v4[2 * (lane + 32) + 1];     \
        _Pragma("unroll")                                                          \
        for (int rg = 0; rg < 8; ++rg) {                                           \
            const int row0 = w * 32 + rg * 4;                                      \
            const size_t rb = (size_t)row0 * (NC / 8) + (size_t)(bid * (CPB / 8)); \
            const uint4* K4 = (const uint4*)g_K  + rb;                             \
            const uint4* Q4 = (const uint4*)g_KM + rb;                             \
            float s0 = 0, s1 = 0, s2 = 0, s3 = 0, q0 = 0, q1 = 0, q2 = 0, q3 = 0;  \
            _Pragma("unroll")                                                      \
            for (int ci = 0; ci < 2; ++ci) {                                       \
                const int c = lane + 32 * ci;                                      \
                uint4 ka = __ldcg(&K4[0 * (NC / 8) + c]);                          \
                uint4 kb = __ldcg(&K4[1 * (NC / 8) + c]);                          \
                uint4 kc = __ldcg(&K4[2 * (NC / 8) + c]);                          \
                uint4 kd = __ldcg(&K4[3 * (NC / 8) + c]);                          \
                uint4 qa = __ldcg(&Q4[0 * (NC / 8) + c]);                          \
                uint4 qb = __ldcg(&Q4[1 * (NC / 8) + c]);                          \
                uint4 qc = __ldcg(&Q4[2 * (NC / 8) + c]);                          \
                uint4 qd = __ldcg(&Q4[3 * (NC / 8) + c]);                          \
                const float4 va = ci ? va1 : va0;                                  \
                const float4 vb = ci ? vb1 : vb0;                                  \
                s0 += dot8(ka, va, vb); s1 += dot8(kb, va, vb);                    \
                s2 += dot8(kc, va, vb); s3 += dot8(kd, va, vb);                    \
                q0 += dot8(qa, va, vb); q1 += dot8(qb, va, vb);                    \
                q2 += dot8(qc, va, vb); q3 += dot8(qd, va, vb);                    \
            }                                                                      \
            _Pragma("unroll")                                                      \
            for (int o = 16; o; o >>= 1) {                                         \
                s0 += __shfl_down_sync(0xffffffffu, s0, o);                        \
                s1 += __shfl_down_sync(0xffffffffu, s1, o);                        \
                s2 += __shfl_down_sync(0xffffffffu, s2, o);                        \
                s3 += __shfl_down_sync(0xffffffffu, s3, o);                        \
                q0 += __shfl_down_sync(0xffffffffu, q0, o);                        \
                q1 += __shfl_down_sync(0xffffffffu, q1, o);                        \
                q2 += __shfl_down_sync(0xffffffffu, q2, o);                        \
                q3 += __shfl_down_sync(0xffffffffu, q3, o);                        \
            }                                                                      \
            if (lane == 0) {                                                       \
                g_sPart[bid * NR + row0 + 0] = s0; g_qPart[bid * NR + row0 + 0] = q0; \
                g_sPart[bid * NR + row0 + 1] = s1; g_qPart[bid * NR + row0 + 1] = q1; \
                g_sPart[bid * NR + row0 + 2] = s2; g_qPart[bid * NR + row0 + 2] = q2; \
                g_sPart[bid * NR + row0 + 3] = s3; g_qPart[bid * NR + row0 + 3] = q3; \
            }                                                                      \
        }                                                                          \
        gsync(phase);                                                              \
        {                                                                          \
            const int row2 = bid * 4 + rr4;                                        \
            float su = __ldcg(&g_sPart[p128 * NR + row2]);                         \
            float qu = __ldcg(&g_qPart[p128 * NR + row2]);                         \
            sh[tid] = su; sh2[tid] = qu; __syncthreads();                          \
            if (p128 < 64) { sh[tid] += sh[tid + 64]; sh2[tid] += sh2[tid + 64]; } \
            __syncthreads();                                                       \
            if (p128 < 32) {                                                       \
                float x = sh[tid] + sh[tid + 32];                                  \
                float y = sh2[tid] + sh2[tid + 32];                                \
                _Pragma("unroll")                                                  \
                for (int o = 16; o; o >>= 1) {                                     \
                    x += __shfl_down_sync(0xffffffffu, x, o);                      \
                    y += __shfl_down_sync(0xffffffffu, y, o);                      \
                }                                                                  \
                if (p128 == 0) {                                                   \
                    float ur = (1.0f / NR) / (x + 1e-16f);                         \
                    g_u[row2] = ur;                                                \
                    sh_l4[rr4] = ur * y;                                           \
                }                                                                  \
            }                                                                      \
            __syncthreads();                                                       \
            if (tid == 0)                                                          \
                g_lossPart[bid] = (sh_l4[0] + sh_l4[1]) + (sh_l4[2] + sh_l4[3]);   \
            gsync(phase);                                                          \
        }                                                                          \
    }

    // ---- column pass (row-major): tp_j = sum_i u_i K_ij via 16 per-thread column
    // accumulators + smem cross-warp reduce. DO_ERR adds err check + verdict.
    #define COL_PASS(DO_ERR, done_var)                                             \
    {                                                                              \
        sh_u[tid] = __ldcg(&g_u[tid]); __syncthreads();                            \
        float tp[16];                                                              \
        _Pragma("unroll")                                                          \
        for (int i = 0; i < 16; ++i) tp[i] = 0.0f;                                 \
        _Pragma("unroll 4")                                                        \
        for (int r = 0; r < 32; ++r) {                                             \
            const int row = w * 32 + r;                                            \
            const uint4* K4 = (const uint4*)g_K + (size_t)row * (NC / 8)           \
                              + (size_t)(bid * (CPB / 8));                         \
            const float u = sh_u[row];                                             \
            uint4 ka = __ldcg(&K4[lane]);                                          \
            uint4 kb = __ldcg(&K4[lane + 32]);                                     \
            float2 f;                                                              \
            f = h2f(ka.x); tp[0]  = fmaf(u, f.x, tp[0]);  tp[1]  = fmaf(u, f.y, tp[1]); \
            f = h2f(ka.y); tp[2]  = fmaf(u, f.x, tp[2]);  tp[3]  = fmaf(u, f.y, tp[3]); \
            f = h2f(ka.z); tp[4]  = fmaf(u, f.x, tp[4]);  tp[5]  = fmaf(u, f.y, tp[5]); \
            f = h2f(ka.w); tp[6]  = fmaf(u, f.x, tp[6]);  tp[7]  = fmaf(u, f.y, tp[7]); \
            f = h2f(kb.x); tp[8]  = fmaf(u, f.x, tp[8]);  tp[9]  = fmaf(u, f.y, tp[9]); \
            f = h2f(kb.y); tp[10] = fmaf(u, f.x, tp[10]); tp[11] = fmaf(u, f.y, tp[11]); \
            f = h2f(kb.z); tp[12] = fmaf(u, f.x, tp[12]); tp[13] = fmaf(u, f.y, tp[13]); \
            f = h2f(kb.w); tp[14] = fmaf(u, f.x, tp[14]); tp[15] = fmaf(u, f.y, tp[15]); \
        }                                                                          \
        _Pragma("unroll")                                                          \
        for (int q = 0; q < 8; ++q) {                                              \
            shcol[w][lane * 8 + q]        = tp[q];                                 \
            shcol[w][(lane + 32) * 8 + q] = tp[8 + q];                             \
        }                                                                          \
        __syncthreads();                                                           \
        float tpj = 0.0f;                                                          \
        _Pragma("unroll")                                                          \
        for (int w2 = 0; w2 < 16; ++w2) tpj += shcol[w2][tid];                     \
        float vn = (1.0f / NC) / (tpj + 1e-16f);                                   \
        if (DO_ERR) {                                                              \
            float e = fabsf(sh_v[tid] * tpj - (1.0f / NC));                        \
            float eb = blockReduce512(e, sh);                                      \
            if (tid == 0) g_errPart[bid] = eb;                                     \
            gsync(phase);                                                          \
            if (bid == 0) {                                                        \
                float ep = (tid < GRID) ? __ldcg(&g_errPart[tid]) : 0.0f;          \
                float et = blockReduce512(ep, sh);                                 \
                int dn = (et <= 0.005f);                                           \
                if (dn) {                                                          \
                    float lp = (tid < GRID) ? __ldcg(&g_lossPart[tid]) : 0.0f;     \
                    float lt = blockReduce512(lp, sh);                             \
                    if (tid == 0) out[0] = 100.0f * lt;                            \
                }                                                                  \
                if (tid == 0) g_done = dn;                                         \
            }                                                                      \
            gsync(phase);                                                          \
            done_var = __ldcg(&g_done);                                            \
        }                                                                          \
        __syncthreads();                                                           \
        sh_v[tid] = vn;                                                            \
        __syncthreads();                                                           \
    }

    // ===== c = 1: phase C -> u_1 (+loss); err check (4 gsyncs on fast path) =====
    PHASE_C();
    int done = 0;
    COL_PASS(1, done);
    if (done) return;                         // trip-1 fast path ends here

    // ===== c = 2..100 (dead for this input; kept correct) =====
    for (int c = 2; c <= 100; ++c) {
        if (c != 2 && c != 52) {
            int dummy = 0;
            COL_PASS(0, dummy);               // phase A: v_c from K
        } // c==2 / c==52: v already produced by COL_PASS(1, ...)

        PHASE_C();                            // u_c (+ loss partials)

        if (c == 51) {
            COL_PASS(1, done);
            if (done) return;
        }
    }

    // ===== cap exit (cpt=100): loss partials from last PHASE_C =====
    if (bid == 0) {
        float lp = (tid < GRID) ? __ldcg(&g_lossPart[tid]) : 0.0f;
        float lt = blockReduce512(lp, sh);
        if (tid == 0) out[0] = 100.0f * lt;
    }
}

extern "C" void kernel_launch(void* const* d_in, const int* in_sizes, int n_in,
                              void* d_out, int out_size) {
    const float* M = (const float*)d_in[0];
    float* out = (float*)d_out;
    sinkhorn_all<<<GRID, TPB>>>(M, out);
}

// round 14
// speedup vs baseline: 1.8714x; 1.2036x over previous
#include <cuda_runtime.h>
#include <cuda_fp16.h>

// M is [512, 65536] fp32. Sinkhorn; trip count in {1, 51, 100}; this input exits at 1.
// R14: pass 1 streams M once (DRAM) and stores ONLY fp16 K=exp(-20M) (64MB, fits L2
// with headroom). Phase C reads K with deep MLP and recovers the loss integrand via
// m=-ln(k)/20 (MUFU log is ~7us chip-wide - measured cheap). Col pass is row-major
// coalesced. Objective: minimize DRAM bytes (~200MB vs R13's 413MB).
#define NR    512
#define NC    65536
#define GRID  128              // <= SM count: wave-1 co-residency guaranteed
#define TPB   512
#define CPB   512              // columns per block (full column stripe)

// Persistent scratch (__device__ globals per allocation rule)
__device__ __half   g_K[(size_t)NR * NC];   // 64 MB fp16 kernel matrix (L2-resident)
__device__ float    g_sPart[GRID * NR];     // row partials of K.v
__device__ float    g_qPart[GRID * NR];     // row partials of (K*m).v (loss, pre-scaled)
__device__ float    g_u[NR];
__device__ float    g_errPart[GRID];
__device__ float    g_lossPart[GRID];
__device__ int      g_done;
__device__ unsigned g_bar = 0;
__device__ volatile unsigned g_gen = 0;     // monotone across graph replays

// Grid barrier: GRID <= #SMs -> cannot deadlock. Spin cap = escape hatch only.
__device__ __forceinline__ void gsync(unsigned &phase) {
    __syncthreads();
    if (threadIdx.x == 0) {
        ++phase;
        __threadfence();
        if (atomicAdd(&g_bar, 1u) == GRID - 1u) {
            g_bar = 0u;
            __threadfence();
            g_gen = phase;
        } else {
            unsigned spins = 0;
            while (g_gen < phase) {
                __nanosleep(64);
                if (++spins > (1u << 18)) break;
            }
        }
    }
    __syncthreads();
}

__device__ __forceinline__ float blockReduce512(float x, float* sh) {
    const int t = threadIdx.x;
    sh[t] = x; __syncthreads();
    if (t < 256) sh[t] += sh[t + 256];
    __syncthreads();
    if (t < 128) sh[t] += sh[t + 128];
    __syncthreads();
    if (t < 64)  sh[t] += sh[t + 64];
    __syncthreads();
    if (t < 32) {
        float v = sh[t] + sh[t + 32];
        #pragma unroll
        for (int o = 16; o; o >>= 1) v += __shfl_down_sync(0xffffffffu, v, o);
        if (t == 0) sh[0] = v;
    }
    __syncthreads();
    float r = sh[0];
    __syncthreads();
    return r;
}

// 2 halfs packed in a u32 -> float2 (constant-index access only; no lmem)
__device__ __forceinline__ float2 h2f(unsigned v) {
    union { unsigned u; __half2 h; } cv; cv.u = v;
    return __half22float2(cv.h);
}
// dot of 8 packed halfs (uint4) with 8 floats (2x float4)
__device__ __forceinline__ float dot8(uint4 kk, float4 va, float4 vb) {
    float2 f0 = h2f(kk.x), f1 = h2f(kk.y), f2 = h2f(kk.z), f3 = h2f(kk.w);
    float s = f3.y * vb.w;
    s = fmaf(f3.x, vb.z, s); s = fmaf(f2.y, vb.y, s); s = fmaf(f2.x, vb.x, s);
    s = fmaf(f1.y, va.w, s); s = fmaf(f1.x, va.z, s);
    s = fmaf(f0.y, va.y, s); s = fmaf(f0.x, va.x, s);
    return s;
}
// loss integrand dot: sum k*ln(max(k,eps)) * v  (scaled by -0.05 at store)
__device__ __forceinline__ float dot8q(uint4 kk, float4 va, float4 vb) {
    float2 f0 = h2f(kk.x), f1 = h2f(kk.y), f2 = h2f(kk.z), f3 = h2f(kk.w);
    float q = f3.y * __logf(fmaxf(f3.y, 1e-38f)) * vb.w;
    q = fmaf(f3.x * __logf(fmaxf(f3.x, 1e-38f)), vb.z, q);
    q = fmaf(f2.y * __logf(fmaxf(f2.y, 1e-38f)), vb.y, q);
    q = fmaf(f2.x * __logf(fmaxf(f2.x, 1e-38f)), vb.x, q);
    q = fmaf(f1.y * __logf(fmaxf(f1.y, 1e-38f)), va.w, q);
    q = fmaf(f1.x * __logf(fmaxf(f1.x, 1e-38f)), va.z, q);
    q = fmaf(f0.y * __logf(fmaxf(f0.y, 1e-38f)), va.y, q);
    q = fmaf(f0.x * __logf(fmaxf(f0.x, 1e-38f)), va.x, q);
    return q;
}

__global__ void __launch_bounds__(TPB, 1)
sinkhorn_all(const float* __restrict__ M, float* __restrict__ out) {
    __shared__ float sh[TPB];
    __shared__ float sh2[TPB];
    __shared__ float sh_u[NR];
    __shared__ float sh_v[CPB];        // this block's v stripe
    __shared__ float shcol[16][CPB];   // cross-warp column-partial staging (32KB)
    __shared__ float sh_l4[4];
    const int tid = threadIdx.x;
    const int bid = blockIdx.x;
    unsigned phase = g_gen;            // continue barrier generation across replays

    const int w    = tid >> 5, lane = tid & 31;
    const int rr4  = tid >> 7, p128 = tid & 127;   // u-reduce mapping (4 rows/block)

    // ===== pass 1: stream M row-major (evict-first), store fp16 K only,
    // accumulate per-thread column sums -> v1. The ONLY exp in the kernel. =====
    {
        float t16[16];
        #pragma unroll
        for (int i = 0; i < 16; ++i) t16[i] = 0.0f;
        #pragma unroll 2
        for (int r = 0; r < 32; ++r) {
            const int row = w * 32 + r;
            const float4* m4 = (const float4*)(M + (size_t)row * NC + bid * CPB);
            uint2* kp = (uint2*)(g_K + (size_t)row * NC + bid * CPB);
            #pragma unroll
            for (int g = 0; g < 4; ++g) {
                const int i = lane + 32 * g;
                float4 m = __ldcs(&m4[i]);
                float k0 = __expf(-20.0f * m.x);
                float k1 = __expf(-20.0f * m.y);
                float k2 = __expf(-20.0f * m.z);
                float k3 = __expf(-20.0f * m.w);
                t16[4 * g + 0] += k0; t16[4 * g + 1] += k1;
                t16[4 * g + 2] += k2; t16[4 * g + 3] += k3;
                union { __half2 h; unsigned u; } a, b;
                a.h = __floats2half2_rn(k0, k1);
                b.h = __floats2half2_rn(k2, k3);
                kp[i] = make_uint2(a.u, b.u);
            }
        }
        #pragma unroll
        for (int g = 0; g < 4; ++g)
            #pragma unroll
            for (int q = 0; q < 4; ++q)
                shcol[w][(lane + 32 * g) * 4 + q] = t16[4 * g + q];
        __syncthreads();
        float t = 0.0f;
        #pragma unroll
        for (int w2 = 0; w2 < 16; ++w2) t += shcol[w2][tid];
        sh_v[tid] = (1.0f / NC) / (t * (1.0f / NR) + 1e-16f);
        __syncthreads();
    }

    // ---- phase C: row partials of K.v and (K*m).v over own stripe (L2 hits).
    // 8-row batches -> 8 independent uint4 loads in flight; v hoisted to regs.
    // m recovered as -ln(k)/20 (applied as -0.05 scale at store).
    #define PHASE_C()                                                              \
    {                                                                              \
        const float4* v4 = (const float4*)sh_v;                                    \
        const float4 va0 = v4[2 * lane],        vb0 = v4[2 * lane + 1];            \
        const float4 va1 = v4[2 * (lane + 32)], vb1 = v4[2 * (lane + 32) + 1];     \
        _Pragma("unroll")                                                          \
        for (int rg = 0; rg < 4; ++rg) {                                           \
            const int row0 = w * 32 + rg * 8;                                      \
            const uint4* K4 = (const uint4*)g_K + (size_t)row0 * (NC / 8)          \
                              + (size_t)(bid * (CPB / 8));                         \
            float s0 = 0, s1 = 0, s2 = 0, s3 = 0, s4 = 0, s5 = 0, s6 = 0, s7 = 0;  \
            float q0 = 0, q1 = 0, q2 = 0, q3 = 0, q4 = 0, q5 = 0, q6 = 0, q7 = 0;  \
            _Pragma("unroll")                                                      \
            for (int ci = 0; ci < 2; ++ci) {                                       \
                const int c = lane + 32 * ci;                                      \
                uint4 ka = __ldcg(&K4[0 * (NC / 8) + c]);                          \
                uint4 kb = __ldcg(&K4[1 * (NC / 8) + c]);                          \
                uint4 kc = __ldcg(&K4[2 * (NC / 8) + c]);                          \
                uint4 kd = __ldcg(&K4[3 * (NC / 8) + c]);                          \
                uint4 ke = __ldcg(&K4[4 * (NC / 8) + c]);                          \
                uint4 kf = __ldcg(&K4[5 * (NC / 8) + c]);                          \
                uint4 kg = __ldcg(&K4[6 * (NC / 8) + c]);                          \
                uint4 kh = __ldcg(&K4[7 * (NC / 8) + c]);                          \
                const float4 va = ci ? va1 : va0;                                  \
                const float4 vb = ci ? vb1 : vb0;                                  \
                s0 += dot8(ka, va, vb); q0 += dot8q(ka, va, vb);                   \
                s1 += dot8(kb, va, vb); q1 += dot8q(kb, va, vb);                   \
                s2 += dot8(kc, va, vb); q2 += dot8q(kc, va, vb);                   \
                s3 += dot8(kd, va, vb); q3 += dot8q(kd, va, vb);                   \
                s4 += dot8(ke, va, vb); q4 += dot8q(ke, va, vb);                   \
                s5 += dot8(kf, va, vb); q5 += dot8q(kf, va, vb);                   \
                s6 += dot8(kg, va, vb); q6 += dot8q(kg, va, vb);                   \
                s7 += dot8(kh, va, vb); q7 += dot8q(kh, va, vb);                   \
            }                                                                      \
            _Pragma("unroll")                                                      \
            for (int o = 16; o; o >>= 1) {                                         \
                s0 += __shfl_down_sync(0xffffffffu, s0, o);                        \
                s1 += __shfl_down_sync(0xffffffffu, s1, o);                        \
                s2 += __shfl_down_sync(0xffffffffu, s2, o);                        \
                s3 += __shfl_down_sync(0xffffffffu, s3, o);                        \
                s4 += __shfl_down_sync(0xffffffffu, s4, o);                        \
                s5 += __shfl_down_sync(0xffffffffu, s5, o);                        \
                s6 += __shfl_down_sync(0xffffffffu, s6, o);                        \
                s7 += __shfl_down_sync(0xffffffffu, s7, o);                        \
                q0 += __shfl_down_sync(0xffffffffu, q0, o);                        \
                q1 += __shfl_down_sync(0xffffffffu, q1, o);                        \
                q2 += __shfl_down_sync(0xffffffffu, q2, o);                        \
                q3 += __shfl_down_sync(0xffffffffu, q3, o);                        \
                q4 += __shfl_down_sync(0xffffffffu, q4, o);                        \
                q5 += __shfl_down_sync(0xffffffffu, q5, o);                        \
                q6 += __shfl_down_sync(0xffffffffu, q6, o);                        \
                q7 += __shfl_down_sync(0xffffffffu, q7, o);                        \
            }                                                                      \
            if (lane == 0) {                                                       \
                const int rbse = bid * NR + row0;                                  \
                g_sPart[rbse + 0] = s0; g_qPart[rbse + 0] = -0.05f * q0;           \
                g_sPart[rbse + 1] = s1; g_qPart[rbse + 1] = -0.05f * q1;           \
                g_sPart[rbse + 2] = s2; g_qPart[rbse + 2] = -0.05f * q2;           \
                g_sPart[rbse + 3] = s3; g_qPart[rbse + 3] = -0.05f * q3;           \
                g_sPart[rbse + 4] = s4; g_qPart[rbse + 4] = -0.05f * q4;           \
                g_sPart[rbse + 5] = s5; g_qPart[rbse + 5] = -0.05f * q5;           \
                g_sPart[rbse + 6] = s6; g_qPart[rbse + 6] = -0.05f * q6;           \
                g_sPart[rbse + 7] = s7; g_qPart[rbse + 7] = -0.05f * q7;           \
            }                                                                      \
        }                                                                          \
        gsync(phase);                                                              \
        {                                                                          \
            const int row2 = bid * 4 + rr4;                                        \
            float su = __ldcg(&g_sPart[p128 * NR + row2]);                         \
            float qu = __ldcg(&g_qPart[p128 * NR + row2]);                         \
            sh[tid] = su; sh2[tid] = qu; __syncthreads();                          \
            if (p128 < 64) { sh[tid] += sh[tid + 64]; sh2[tid] += sh2[tid + 64]; } \
            __syncthreads();                                                       \
            if (p128 < 32) {                                                       \
                float x = sh[tid] + sh[tid + 32];                                  \
                float y = sh2[tid] + sh2[tid + 32];                                \
                _Pragma("unroll")                                                  \
                for (int o = 16; o; o >>= 1) {                                     \
                    x += __shfl_down_sync(0xffffffffu, x, o);                      \
                    y += __shfl_down_sync(0xffffffffu, y, o);                      \
                }                                                                  \
                if (p128 == 0) {                                                   \
                    float ur = (1.0f / NR) / (x + 1e-16f);                         \
                    g_u[row2] = ur;                                                \
                    sh_l4[rr4] = ur * y;                                           \
                }                                                                  \
            }                                                                      \
            __syncthreads();                                                       \
            if (tid == 0)                                                          \
                g_lossPart[bid] = (sh_l4[0] + sh_l4[1]) + (sh_l4[2] + sh_l4[3]);   \
            gsync(phase);                                                          \
        }                                                                          \
    }

    // ---- column pass (row-major): tp_j = sum_i u_i K_ij via 16 per-thread column
    // accumulators + smem cross-warp reduce. DO_ERR adds err check + verdict.
    #define COL_PASS(DO_ERR, done_var)                                             \
    {                                                                              \
        sh_u[tid] = __ldcg(&g_u[tid]); __syncthreads();                            \
        float tp[16];                                                              \
        _Pragma("unroll")                                                          \
        for (int i = 0; i < 16; ++i) tp[i] = 0.0f;                                 \
        _Pragma("unroll 4")                                                        \
        for (int r = 0; r < 32; ++r) {                                             \
            const int row = w * 32 + r;                                            \
            const uint4* K4 = (const uint4*)g_K + (size_t)row * (NC / 8)           \
                              + (size_t)(bid * (CPB / 8));                         \
            const float u = sh_u[row];                                             \
            uint4 ka = __ldcg(&K4[lane]);                                          \
            uint4 kb = __ldcg(&K4[lane + 32]);                                     \
            float2 f;                                                              \
            f = h2f(ka.x); tp[0]  = fmaf(u, f.x, tp[0]);  tp[1]  = fmaf(u, f.y, tp[1]); \
            f = h2f(ka.y); tp[2]  = fmaf(u, f.x, tp[2]);  tp[3]  = fmaf(u, f.y, tp[3]); \
            f = h2f(ka.z); tp[4]  = fmaf(u, f.x, tp[4]);  tp[5]  = fmaf(u, f.y, tp[5]); \
            f = h2f(ka.w); tp[6]  = fmaf(u, f.x, tp[6]);  tp[7]  = fmaf(u, f.y, tp[7]); \
            f = h2f(kb.x); tp[8]  = fmaf(u, f.x, tp[8]);  tp[9]  = fmaf(u, f.y, tp[9]); \
            f = h2f(kb.y); tp[10] = fmaf(u, f.x, tp[10]); tp[11] = fmaf(u, f.y, tp[11]); \
            f = h2f(kb.z); tp[12] = fmaf(u, f.x, tp[12]); tp[13] = fmaf(u, f.y, tp[13]); \
            f = h2f(kb.w); tp[14] = fmaf(u, f.x, tp[14]); tp[15] = fmaf(u, f.y, tp[15]); \
        }                                                                          \
        _Pragma("unroll")                                                          \
        for (int q = 0; q < 8; ++q) {                                              \
            shcol[w][lane * 8 + q]        = tp[q];                                 \
            shcol[w][(lane + 32) * 8 + q] = tp[8 + q];                             \
        }                                                                          \
        __syncthreads();                                                           \
        float tpj = 0.0f;                                                          \
        _Pragma("unroll")                                                          \
        for (int w2 = 0; w2 < 16; ++w2) tpj += shcol[w2][tid];                     \
        float vn = (1.0f / NC) / (tpj + 1e-16f);                                   \
        if (DO_ERR) {                                                              \
            float e = fabsf(sh_v[tid] * tpj - (1.0f / NC));                        \
            float eb = blockReduce512(e, sh);                                      \
            if (tid == 0) g_errPart[bid] = eb;                                     \
            gsync(phase);                                                          \
            if (bid == 0) {                                                        \
                float ep = (tid < GRID) ? __ldcg(&g_errPart[tid]) : 0.0f;          \
                float et = blockReduce512(ep, sh);                                 \
                int dn = (et <= 0.005f);                                           \
                if (dn) {                                                          \
                    float lp = (tid < GRID) ? __ldcg(&g_lossPart[tid]) : 0.0f;     \
                    float lt = blockReduce512(lp, sh);                             \
                    if (tid == 0) out[0] = 100.0f * lt;                            \
                }                                                                  \
                if (tid == 0) g_done = dn;                                         \
            }                                                                      \
            gsync(phase);                                                          \
            done_var = __ldcg(&g_done);                                            \
        }                                                                          \
        __syncthreads();                                                           \
        sh_v[tid] = vn;                                                            \
        __syncthreads();                                                           \
    }

    // ===== c = 1: phase C -> u_1 (+loss); err check (4 gsyncs on fast path) =====
    PHASE_C();
    int done = 0;
    COL_PASS(1, done);
    if (done) return;                         // trip-1 fast path ends here

    // ===== c = 2..100 (dead for this input; kept correct) =====
    for (int c = 2; c <= 100; ++c) {
        if (c != 2 && c != 52) {
            int dummy = 0;
            COL_PASS(0, dummy);               // phase A: v_c from K
        } // c==2 / c==52: v already produced by COL_PASS(1, ...)

        PHASE_C();                            // u_c (+ loss partials)

        if (c == 51) {
            COL_PASS(1, done);
            if (done) return;
        }
    }

    // ===== cap exit (cpt=100): loss partials from last PHASE_C =====
    if (bid == 0) {
        float lp = (tid < GRID) ? __ldcg(&g_lossPart[tid]) : 0.0f;
        float lt = blockReduce512(lp, sh);
        if (tid == 0) out[0] = 100.0f * lt;
    }
}

extern "C" void kernel_launch(void* const* d_in, const int* in_sizes, int n_in,
                              void* d_out, int out_size) {
    const float* M = (const float*)d_in[0];
    float* out = (float*)d_out;
    sinkhorn_all<<<GRID, TPB>>>(M, out);
}

// round 15
// speedup vs baseline: 3.1876x; 1.7034x over previous
#include <cuda_runtime.h>
#include <cuda_fp16.h>

// M is [512, 65536] fp32. Sinkhorn; trip {1,51,100}; this input exits at 1.
// R15 = R14 byte-minimal design (single M stream -> fp16 K in L2; loss via
// m=-ln(k)/20) with latency exposure stripped: 2 gsyncs + 1 tagged broadcast,
// local-full u reduce, pipelined pass 1 with STG.128, log2-based loss dot.
#define NR    512
#define NC    65536
#define GRID  128              // <= SM count: wave-1 co-residency guaranteed
#define TPB   512
#define CPB   512              // columns per block

__device__ __half   g_K[(size_t)NR * NC];      // 64 MB fp16 K (L2-resident)
__device__ float    g_sPart[2][GRID * NR];     // parity-buffered row partials K.v
__device__ float    g_qPart[2][GRID * NR];     // parity-buffered row partials (K*m).v
__device__ float    g_errPart[GRID];
__device__ float    g_lossPart[GRID];
__device__ unsigned g_bar = 0;
__device__ volatile unsigned g_gen = 0;        // monotone across graph replays
__device__ volatile unsigned g_verdict = 0;    // (tag<<1)|done, tag monotone

__device__ __forceinline__ void gsync(unsigned &phase) {
    __syncthreads();
    if (threadIdx.x == 0) {
        ++phase;
        __threadfence();
        if (atomicAdd(&g_bar, 1u) == GRID - 1u) {
            g_bar = 0u;
            __threadfence();
            g_gen = phase;
        } else {
            unsigned spins = 0;
            while (g_gen < phase) {
                __nanosleep(32);
                if (++spins > (1u << 19)) break;   // escape hatch
            }
        }
    }
    __syncthreads();
}

__device__ __forceinline__ float blockReduce512(float x, float* sh) {
    const int t = threadIdx.x;
    sh[t] = x; __syncthreads();
    if (t < 256) sh[t] += sh[t + 256];
    __syncthreads();
    if (t < 128) sh[t] += sh[t + 128];
    __syncthreads();
    if (t < 64)  sh[t] += sh[t + 64];
    __syncthreads();
    if (t < 32) {
        float v = sh[t] + sh[t + 32];
        #pragma unroll
        for (int o = 16; o; o >>= 1) v += __shfl_down_sync(0xffffffffu, v, o);
        if (t == 0) sh[0] = v;
    }
    __syncthreads();
    float r = sh[0];
    __syncthreads();
    return r;
}

__device__ __forceinline__ float2 h2f(unsigned v) {
    union { unsigned u; __half2 h; } cv; cv.u = v;
    return __half22float2(cv.h);
}
__device__ __forceinline__ float dot8(uint4 kk, float4 va, float4 vb) {
    float2 f0 = h2f(kk.x), f1 = h2f(kk.y), f2 = h2f(kk.z), f3 = h2f(kk.w);
    float s = f3.y * vb.w;
    s = fmaf(f3.x, vb.z, s); s = fmaf(f2.y, vb.y, s); s = fmaf(f2.x, vb.x, s);
    s = fmaf(f1.y, va.w, s); s = fmaf(f1.x, va.z, s);
    s = fmaf(f0.y, va.y, s); s = fmaf(f0.x, va.x, s);
    return s;
}
// sum k*log2(max(k,eps))*v; caller scales by -0.05*ln2
__device__ __forceinline__ float dot8q(uint4 kk, float4 va, float4 vb) {
    float2 f0 = h2f(kk.x), f1 = h2f(kk.y), f2 = h2f(kk.z), f3 = h2f(kk.w);
    float q = f3.y * __log2f(fmaxf(f3.y, 1e-38f)) * vb.w;
    q = fmaf(f3.x * __log2f(fmaxf(f3.x, 1e-38f)), vb.z, q);
    q = fmaf(f2.y * __log2f(fmaxf(f2.y, 1e-38f)), vb.y, q);
    q = fmaf(f2.x * __log2f(fmaxf(f2.x, 1e-38f)), vb.x, q);
    q = fmaf(f1.y * __log2f(fmaxf(f1.y, 1e-38f)), va.w, q);
    q = fmaf(f1.x * __log2f(fmaxf(f1.x, 1e-38f)), va.z, q);
    q = fmaf(f0.y * __log2f(fmaxf(f0.y, 1e-38f)), va.y, q);
    q = fmaf(f0.x * __log2f(fmaxf(f0.x, 1e-38f)), va.x, q);
    return q;
}
#define QSCALE (-0.034657359027997264f)   // -0.05 * ln(2)

__global__ void __launch_bounds__(TPB, 1)
sinkhorn_all(const float* __restrict__ M, float* __restrict__ out) {
    __shared__ float sh[TPB];
    __shared__ float sh_u[NR];
    __shared__ float sh_v[CPB];
    __shared__ float shcol[16][CPB];   // 32 KB staging
    __shared__ float sh_l4[4];
    __shared__ int   sh_done;
    const int tid = threadIdx.x;
    const int bid = blockIdx.x;
    unsigned phase = g_gen;            // continue barrier generation across replays

    const int w = tid >> 5, lane = tid & 31;
    const int rr4 = tid >> 7, p128 = tid & 127;

    // ===== pass 1: stream M (evict-first), store fp16 K (STG.128), col sums -> v1.
    // Thread covers 8 consecutive floats at 2 positions per row; 2-row batches. =====
    {
        float t16[16];
        #pragma unroll
        for (int i = 0; i < 16; ++i) t16[i] = 0.0f;
        #pragma unroll 2
        for (int rp = 0; rp < 16; ++rp) {      // 2 rows per iteration
            const int row0 = w * 32 + rp * 2;
            const float4* m40 = (const float4*)(M + (size_t)row0 * NC + bid * CPB);
            const float4* m41 = (const float4*)(M + (size_t)(row0 + 1) * NC + bid * CPB);
            float4 a0 = __ldcs(&m40[2 * lane]);
            float4 a1 = __ldcs(&m40[2 * lane + 1]);
            float4 b0 = __ldcs(&m40[2 * (lane + 32)]);
            float4 b1 = __ldcs(&m40[2 * (lane + 32) + 1]);
            float4 c0 = __ldcs(&m41[2 * lane]);
            float4 c1 = __ldcs(&m41[2 * lane + 1]);
            float4 d0 = __ldcs(&m41[2 * (lane + 32)]);
            float4 d1 = __ldcs(&m41[2 * (lane + 32) + 1]);
            uint4* kp0 = (uint4*)(g_K + (size_t)row0 * NC + bid * CPB);
            uint4* kp1 = (uint4*)(g_K + (size_t)(row0 + 1) * NC + bid * CPB);
            #define EXP8(v0, v4, K0, K1, K2, K3, K4, K5, K6, K7)                   \
                float K0 = __expf(-20.0f * v0.x), K1 = __expf(-20.0f * v0.y);      \
                float K2 = __expf(-20.0f * v0.z), K3 = __expf(-20.0f * v0.w);      \
                float K4 = __expf(-20.0f * v4.x), K5 = __expf(-20.0f * v4.y);      \
                float K6 = __expf(-20.0f * v4.z), K7 = __expf(-20.0f * v4.w);
            #define PACK4(K0, K1, K2, K3, K4, K5, K6, K7)                          \
                make_uint4(__half2_as_u(K0, K1), __half2_as_u(K2, K3),             \
                           __half2_as_u(K4, K5), __half2_as_u(K6, K7))
            #define __half2_as_u(x, y) (__half2_raw(__floats2half2_rn(x, y)).x |   \
                                        ((unsigned)__half2_raw(__floats2half2_rn(x, y)).y << 16))
            // (macro above is clunky; do it inline instead)
            #undef PACK4
            #undef __half2_as_u
            {
                EXP8(a0, a1, ka0, ka1, ka2, ka3, ka4, ka5, ka6, ka7)
                union { __half2 h[2]; uint2 u; } pa, pb;
                pa.h[0] = __floats2half2_rn(ka0, ka1); pa.h[1] = __floats2half2_rn(ka2, ka3);
                pb.h[0] = __floats2half2_rn(ka4, ka5); pb.h[1] = __floats2half2_rn(ka6, ka7);
                kp0[lane] = make_uint4(pa.u.x, pa.u.y, pb.u.x, pb.u.y);
                t16[0] += ka0; t16[1] += ka1; t16[2] += ka2; t16[3] += ka3;
                t16[4] += ka4; t16[5] += ka5; t16[6] += ka6; t16[7] += ka7;
            }
            {
                EXP8(b0, b1, kb0, kb1, kb2, kb3, kb4, kb5, kb6, kb7)
                union { __half2 h[2]; uint2 u; } pa, pb;
                pa.h[0] = __floats2half2_rn(kb0, kb1); pa.h[1] = __floats2half2_rn(kb2, kb3);
                pb.h[0] = __floats2half2_rn(kb4, kb5); pb.h[1] = __floats2half2_rn(kb6, kb7);
                kp0[lane + 32] = make_uint4(pa.u.x, pa.u.y, pb.u.x, pb.u.y);
                t16[8] += kb0; t16[9] += kb1; t16[10] += kb2; t16[11] += kb3;
                t16[12] += kb4; t16[13] += kb5; t16[14] += kb6; t16[15] += kb7;
            }
            {
                EXP8(c0, c1, kc0, kc1, kc2, kc3, kc4, kc5, kc6, kc7)
                union { __half2 h[2]; uint2 u; } pa, pb;
                pa.h[0] = __floats2half2_rn(kc0, kc1); pa.h[1] = __floats2half2_rn(kc2, kc3);
                pb.h[0] = __floats2half2_rn(kc4, kc5); pb.h[1] = __floats2half2_rn(kc6, kc7);
                kp1[lane] = make_uint4(pa.u.x, pa.u.y, pb.u.x, pb.u.y);
                t16[0] += kc0; t16[1] += kc1; t16[2] += kc2; t16[3] += kc3;
                t16[4] += kc4; t16[5] += kc5; t16[6] += kc6; t16[7] += kc7;
            }
            {
                EXP8(d0, d1, kd0, kd1, kd2, kd3, kd4, kd5, kd6, kd7)
                union { __half2 h[2]; uint2 u; } pa, pb;
                pa.h[0] = __floats2half2_rn(kd0, kd1); pa.h[1] = __floats2half2_rn(kd2, kd3);
                pb.h[0] = __floats2half2_rn(kd4, kd5); pb.h[1] = __floats2half2_rn(kd6, kd7);
                kp1[lane + 32] = make_uint4(pa.u.x, pa.u.y, pb.u.x, pb.u.y);
                t16[8] += kd0; t16[9] += kd1; t16[10] += kd2; t16[11] += kd3;
                t16[12] += kd4; t16[13] += kd5; t16[14] += kd6; t16[15] += kd7;
            }
            #undef EXP8
        }
        #pragma unroll
        for (int q = 0; q < 8; ++q) {
            shcol[w][lane * 8 + q]        = t16[q];
            shcol[w][(lane + 32) * 8 + q] = t16[8 + q];
        }
        __syncthreads();
        float t = 0.0f;
        #pragma unroll
        for (int w2 = 0; w2 < 16; ++w2) t += shcol[w2][tid];
        sh_v[tid] = (1.0f / NC) / (t * (1.0f / NR) + 1e-16f);
        __syncthreads();
    }

    // ---- phase C(par): row partials of K.v, (K*m).v; ONE gsync; then local-full
    // u reduce (128 L2 loads/thread) and partitioned loss -> g_lossPart[bid].
    #define PHASE_C(par)                                                           \
    {                                                                              \
        const float4* v4 = (const float4*)sh_v;                                    \
        const float4 va0 = v4[2 * lane],        vb0 = v4[2 * lane + 1];            \
        const float4 va1 = v4[2 * (lane + 32)], vb1 = v4[2 * (lane + 32) + 1];     \
        _Pragma("unroll")                                                          \
        for (int rg = 0; rg < 4; ++rg) {                                           \
            const int row0 = w * 32 + rg * 8;                                      \
            const uint4* K4 = (const uint4*)g_K + (size_t)row0 * (NC / 8)          \
                              + (size_t)(bid * (CPB / 8));                         \
            float s0 = 0, s1 = 0, s2 = 0, s3 = 0, s4 = 0, s5 = 0, s6 = 0, s7 = 0;  \
            float q0 = 0, q1 = 0, q2 = 0, q3 = 0, q4 = 0, q5 = 0, q6 = 0, q7 = 0;  \
            _Pragma("unroll")                                                      \
            for (int ci = 0; ci < 2; ++ci) {                                       \
                const int c = lane + 32 * ci;                                      \
                uint4 ea = __ldcg(&K4[0 * (NC / 8) + c]);                          \
                uint4 eb = __ldcg(&K4[1 * (NC / 8) + c]);                          \
                uint4 ec = __ldcg(&K4[2 * (NC / 8) + c]);                          \
                uint4 ed = __ldcg(&K4[3 * (NC / 8) + c]);                          \
                uint4 ee = __ldcg(&K4[4 * (NC / 8) + c]);                          \
                uint4 ef = __ldcg(&K4[5 * (NC / 8) + c]);                          \
                uint4 eg = __ldcg(&K4[6 * (NC / 8) + c]);                          \
                uint4 eh = __ldcg(&K4[7 * (NC / 8) + c]);                          \
                const float4 va = ci ? va1 : va0;                                  \
                const float4 vb = ci ? vb1 : vb0;                                  \
                s0 += dot8(ea, va, vb); q0 += dot8q(ea, va, vb);                   \
                s1 += dot8(eb, va, vb); q1 += dot8q(eb, va, vb);                   \
                s2 += dot8(ec, va, vb); q2 += dot8q(ec, va, vb);                   \
                s3 += dot8(ed, va, vb); q3 += dot8q(ed, va, vb);                   \
                s4 += dot8(ee, va, vb); q4 += dot8q(ee, va, vb);                   \
                s5 += dot8(ef, va, vb); q5 += dot8q(ef, va, vb);                   \
                s6 += dot8(eg, va, vb); q6 += dot8q(eg, va, vb);                   \
                s7 += dot8(eh, va, vb); q7 += dot8q(eh, va, vb);                   \
            }                                                                      \
            _Pragma("unroll")                                                      \
            for (int o = 16; o; o >>= 1) {                                         \
                s0 += __shfl_down_sync(0xffffffffu, s0, o);                        \
                s1 += __shfl_down_sync(0xffffffffu, s1, o);                        \
                s2 += __shfl_down_sync(0xffffffffu, s2, o);                        \
                s3 += __shfl_down_sync(0xffffffffu, s3, o);                        \
                s4 += __shfl_down_sync(0xffffffffu, s4, o);                        \
                s5 += __shfl_down_sync(0xffffffffu, s5, o);                        \
                s6 += __shfl_down_sync(0xffffffffu, s6, o);                        \
                s7 += __shfl_down_sync(0xffffffffu, s7, o);                        \
                q0 += __shfl_down_sync(0xffffffffu, q0, o);                        \
                q1 += __shfl_down_sync(0xffffffffu, q1, o);                        \
                q2 += __shfl_down_sync(0xffffffffu, q2, o);                        \
                q3 += __shfl_down_sync(0xffffffffu, q3, o);                        \
                q4 += __shfl_down_sync(0xffffffffu, q4, o);                        \
                q5 += __shfl_down_sync(0xffffffffu, q5, o);                        \
                q6 += __shfl_down_sync(0xffffffffu, q6, o);                        \
                q7 += __shfl_down_sync(0xffffffffu, q7, o);                        \
            }                                                                      \
            if (lane == 0) {                                                       \
                const int rb = bid * NR + row0;                                    \
                g_sPart[par][rb + 0] = s0; g_qPart[par][rb + 0] = QSCALE * q0;     \
                g_sPart[par][rb + 1] = s1; g_qPart[par][rb + 1] = QSCALE * q1;     \
                g_sPart[par][rb + 2] = s2; g_qPart[par][rb + 2] = QSCALE * q2;     \
                g_sPart[par][rb + 3] = s3; g_qPart[par][rb + 3] = QSCALE * q3;     \
                g_sPart[par][rb + 4] = s4; g_qPart[par][rb + 4] = QSCALE * q4;     \
                g_sPart[par][rb + 5] = s5; g_qPart[par][rb + 5] = QSCALE * q5;     \
                g_sPart[par][rb + 6] = s6; g_qPart[par][rb + 6] = QSCALE * q6;     \
                g_sPart[par][rb + 7] = s7; g_qPart[par][rb + 7] = QSCALE * q7;     \
            }                                                                      \
        }                                                                          \
        gsync(phase);                                                              \
        {                                                                          \
            float su = 0.0f;                                                       \
            _Pragma("unroll 8")                                                    \
            for (int b = 0; b < GRID; ++b)                                         \
                su += __ldcg(&g_sPart[par][b * NR + tid]);                         \
            sh_u[tid] = (1.0f / NR) / (su + 1e-16f);                               \
            __syncthreads();                                                       \
            const int row2 = bid * 4 + rr4;                                        \
            float qu = __ldcg(&g_qPart[par][p128 * NR + row2]);                    \
            sh[tid] = qu; __syncthreads();                                         \
            if (p128 < 64) sh[tid] += sh[tid + 64];                                \
            __syncthreads();                                                       \
            if (p128 < 32) {                                                       \
                float y = sh[tid] + sh[tid + 32];                                  \
                _Pragma("unroll")                                                  \
                for (int o = 16; o; o >>= 1)                                       \
                    y += __shfl_down_sync(0xffffffffu, y, o);                      \
                if (p128 == 0) sh_l4[rr4] = sh_u[row2] * y;                        \
            }                                                                      \
            __syncthreads();                                                       \
            if (tid == 0)                                                          \
                g_lossPart[bid] = (sh_l4[0] + sh_l4[1]) + (sh_l4[2] + sh_l4[3]);   \
            __syncthreads();                                                       \
        }                                                                          \
    }

    // ---- col pass: tp = K^T u (row-major, 16 per-thread col accumulators).
    // DO_ERR: err partial -> gsync -> block0 verdict -> tagged broadcast.
    #define COL_PASS(DO_ERR, done_var)                                             \
    {                                                                              \
        float tp[16];                                                              \
        _Pragma("unroll")                                                          \
        for (int i = 0; i < 16; ++i) tp[i] = 0.0f;                                 \
        _Pragma("unroll 4")                                                        \
        for (int r = 0; r < 32; ++r) {                                             \
            const int row = w * 32 + r;                                            \
            const uint4* K4 = (const uint4*)g_K + (size_t)row * (NC / 8)           \
                              + (size_t)(bid * (CPB / 8));                         \
            const float u = sh_u[row];                                             \
            uint4 ea = __ldcg(&K4[lane]);                                          \
            uint4 eb = __ldcg(&K4[lane + 32]);                                     \
            float2 f;                                                              \
            f = h2f(ea.x); tp[0]  = fmaf(u, f.x, tp[0]);  tp[1]  = fmaf(u, f.y, tp[1]); \
            f = h2f(ea.y); tp[2]  = fmaf(u, f.x, tp[2]);  tp[3]  = fmaf(u, f.y, tp[3]); \
            f = h2f(ea.z); tp[4]  = fmaf(u, f.x, tp[4]);  tp[5]  = fmaf(u, f.y, tp[5]); \
            f = h2f(ea.w); tp[6]  = fmaf(u, f.x, tp[6]);  tp[7]  = fmaf(u, f.y, tp[7]); \
            f = h2f(eb.x); tp[8]  = fmaf(u, f.x, tp[8]);  tp[9]  = fmaf(u, f.y, tp[9]); \
            f = h2f(eb.y); tp[10] = fmaf(u, f.x, tp[10]); tp[11] = fmaf(u, f.y, tp[11]); \
            f = h2f(eb.z); tp[12] = fmaf(u, f.x, tp[12]); tp[13] = fmaf(u, f.y, tp[13]); \
            f = h2f(eb.w); tp[14] = fmaf(u, f.x, tp[14]); tp[15] = fmaf(u, f.y, tp[15]); \
        }                                                                          \
        __syncthreads();                                                           \
        _Pragma("unroll")                                                          \
        for (int q = 0; q < 8; ++q) {                                              \
            shcol[w][lane * 8 + q]        = tp[q];                                 \
            shcol[w][(lane + 32) * 8 + q] = tp[8 + q];                             \
        }                                                                          \
        __syncthreads();                                                           \
        float tpj = 0.0f;                                                          \
        _Pragma("unroll")                                                          \
        for (int w2 = 0; w2 < 16; ++w2) tpj += shcol[w2][tid];                     \
        float vn = (1.0f / NC) / (tpj + 1e-16f);                                   \
        if (DO_ERR) {                                                              \
            float e = fabsf(sh_v[tid] * tpj - (1.0f / NC));                        \
            float eb2 = blockReduce512(e, sh);                                     \
            if (tid == 0) g_errPart[bid] = eb2;                                    \
            gsync(phase);                                                          \
            ++phase;                       /* broadcast tag slot */                \
            if (bid == 0) {                                                        \
                float ep = (tid < GRID) ? __ldcg(&g_errPart[tid]) : 0.0f;          \
                float et = blockReduce512(ep, sh);                                 \
                int dn = (et <= 0.005f);                                           \
                if (dn) {                                                          \
                    float lp = (tid < GRID) ? __ldcg(&g_lossPart[tid]) : 0.0f;     \
                    float lt = blockReduce512(lp, sh);                             \
                    if (tid == 0) out[0] = 100.0f * lt;                            \
                }                                                                  \
                if (tid == 0) {                                                    \
                    sh_done = dn;                                                  \
                    __threadfence();                                               \
                    g_verdict = (phase << 1) | (unsigned)dn;                       \
                }                                                                  \
            } else if (tid == 0) {                                                 \
                unsigned vv, spins = 0;                                            \
                do {                                                               \
                    vv = *(volatile unsigned*)&g_verdict;                          \
                    if ((vv >> 1) == phase) break;                                 \
                    __nanosleep(32);                                               \
                } while (++spins < (1u << 19));                                    \
                sh_done = (int)(vv & 1u);                                          \
            }                                                                      \
            __syncthreads();                                                       \
            done_var = sh_done;                                                    \
        }                                                                          \
        __syncthreads();                                                           \
        sh_v[tid] = vn;                                                            \
        __syncthreads();                                                           \
    }

    // ===== c = 1: phase C -> u_1 (+loss); err check. 2 gsyncs + 1 broadcast. =====
    PHASE_C(0);
    int done = 0;
    COL_PASS(1, done);
    if (done) return;

    // ===== c = 2..100 (dead for this input; kept correct) =====
    for (int c = 2; c <= 100; ++c) {
        if (c != 2 && c != 52) {
            int dummy = 0;
            COL_PASS(0, dummy);
        }
        PHASE_C(c & 1);
        if (c == 51) {
            COL_PASS(1, done);
            if (done) return;
        }
    }
    gsync(phase);                      // cap exit: make lossPart visible
    if (bid == 0) {
        float lp = (tid < GRID) ? __ldcg(&g_lossPart[tid]) : 0.0f;
        float lt = blockReduce512(lp, sh);
        if (tid == 0) out[0] = 100.0f * lt;
    }
}

extern "C" void kernel_launch(void* const* d_in, const int* in_sizes, int n_in,
                              void* d_out, int out_size) {
    const float* M = (const float*)d_in[0];
    float* out = (float*)d_out;
    sinkhorn_all<<<GRID, TPB>>>(M, out);
}